// round 1
// baseline (speedup 1.0000x reference)
#include <cuda_runtime.h>
#include <cuda_bf16.h>
#include <cstdint>

// Problem constants (fixed by the dataset)
#define BB   8
#define LQ   5440
#define LIN  5440
#define DM   256
#define NH   8
#define NL   4
#define NP   4
#define DH   32
#define MTOT (BB * LQ)   // 43520

// Scratch (device globals; allocation-free per harness rules)
__device__ __align__(16) float g_value[MTOT * DM];
__device__ __align__(16) float g_off  [MTOT * DM];
__device__ __align__(16) float g_attn [MTOT * (NH * NL * NP)];
__device__ __align__(16) float g_core [MTOT * DM];

// ---------------------------------------------------------------------------
// Tiled fp32 SGEMM with bias: C[M,N] = A[M,K] * W[K,N] + b[N]
// BM=BN=128, BK=8, 256 threads, 8x8 per-thread microtile.
// M is always a multiple of 128, N in {128,256}, K=256 -> no bounds checks.
// ---------------------------------------------------------------------------
__global__ __launch_bounds__(256, 2) void sgemm_bias(
    const float* __restrict__ A, const float* __restrict__ W,
    const float* __restrict__ bias, float* __restrict__ C,
    int N, int K)
{
    __shared__ float As[8][128];
    __shared__ float Bs[8][128];

    const int tid = threadIdx.x;
    const int tx  = tid & 15;    // col group 0..15
    const int ty  = tid >> 4;    // row group 0..15
    const long mBase = (long)blockIdx.y * 128;
    const int  nBase = blockIdx.x * 128;

    // A tile load mapping: 128 rows x 8 k; each thread one float4 along k
    const int arow = tid >> 1;
    const int akq  = (tid & 1) * 4;
    // B tile load mapping: 8 k-rows x 128 cols; each thread one float4 along n
    const int brow = tid >> 5;
    const int bcol = (tid & 31) * 4;

    float acc[8][8];
#pragma unroll
    for (int i = 0; i < 8; i++)
#pragma unroll
        for (int j = 0; j < 8; j++) acc[i][j] = 0.f;

    for (int k0 = 0; k0 < K; k0 += 8) {
        float4 av = *(const float4*)(A + (mBase + arow) * K + k0 + akq);
        As[akq + 0][arow] = av.x;
        As[akq + 1][arow] = av.y;
        As[akq + 2][arow] = av.z;
        As[akq + 3][arow] = av.w;
        *(float4*)(&Bs[brow][bcol]) =
            *(const float4*)(W + (long)(k0 + brow) * N + nBase + bcol);
        __syncthreads();

#pragma unroll
        for (int k = 0; k < 8; k++) {
            float a[8], b[8];
#pragma unroll
            for (int i = 0; i < 8; i++) a[i] = As[k][ty * 8 + i];
#pragma unroll
            for (int j = 0; j < 8; j++) b[j] = Bs[k][tx * 8 + j];
#pragma unroll
            for (int i = 0; i < 8; i++)
#pragma unroll
                for (int j = 0; j < 8; j++) acc[i][j] += a[i] * b[j];
        }
        __syncthreads();
    }

#pragma unroll
    for (int i = 0; i < 8; i++) {
        long crow = mBase + ty * 8 + i;
#pragma unroll
        for (int j = 0; j < 8; j += 4) {
            int col = nBase + tx * 8 + j;
            float4 o;
            o.x = acc[i][j + 0] + bias[col + 0];
            o.y = acc[i][j + 1] + bias[col + 1];
            o.z = acc[i][j + 2] + bias[col + 2];
            o.w = acc[i][j + 3] + bias[col + 3];
            *(float4*)(C + crow * N + col) = o;
        }
    }
}

// ---------------------------------------------------------------------------
// Fused softmax + multi-scale deformable sampling.
// One warp per (b, q, head). Lanes 0..15 own one (level, point) each:
// compute sampling location, bilinear corner weights, and softmax weight.
// Then all 32 lanes (one per D_HEAD channel) accumulate 16x4 broadcast
// gathers from g_value (each gather = coalesced 128B line).
// ---------------------------------------------------------------------------
__global__ void msda_sample(const float* __restrict__ refp)
{
    const int gw   = (blockIdx.x * blockDim.x + threadIdx.x) >> 5;
    const int lane = threadIdx.x & 31;
    const int h    = gw & 7;
    const int row  = gw >> 3;          // b*LQ + q
    const int b    = row / LQ;

    // setup lanes (lanes 16..31 duplicate lanes 0..15; harmless, keeps
    // all addresses in-bounds without extra predication)
    const int s   = lane & 15;
    const int lvl = s >> 2;
    const int pt  = s & 3;
    const int Wl  = 64 >> lvl;                               // square levels
    const int st  = (16384 - (16384 >> (2 * lvl))) / 3;      // {0,4096,5120,5376}

    const float refx = refp[row * 8 + lvl * 2 + 0];
    const float refy = refp[row * 8 + lvl * 2 + 1];
    const int obase  = row * 256 + (((h * 4 + lvl) * 4 + pt) * 2);
    const float offx = g_off[obase + 0];
    const float offy = g_off[obase + 1];

    // loc = ref + off/W;  x = loc*W - 0.5  ==  ref*W + off - 0.5
    const float x = refx * (float)Wl + offx - 0.5f;
    const float y = refy * (float)Wl + offy - 0.5f;
    const float fx = floorf(x), fy = floorf(y);
    const float lx = x - fx,   ly = y - fy;
    const int x0 = (int)fx, y0 = (int)fy;
    const int x1 = x0 + 1,  y1 = y0 + 1;

    // softmax over the 16 (level,point) logits of this head
    const float logit = g_attn[row * 128 + h * 16 + s];
    float mx = logit;
#pragma unroll
    for (int o = 8; o; o >>= 1) mx = fmaxf(mx, __shfl_xor_sync(~0u, mx, o, 16));
    const float e = __expf(logit - mx);
    float sum = e;
#pragma unroll
    for (int o = 8; o; o >>= 1) sum += __shfl_xor_sync(~0u, sum, o, 16);
    const float wa = e / sum;

    const bool vx0 = (unsigned)x0 < (unsigned)Wl;
    const bool vx1 = (unsigned)x1 < (unsigned)Wl;
    const bool vy0 = (unsigned)y0 < (unsigned)Wl;
    const bool vy1 = (unsigned)y1 < (unsigned)Wl;
    const int cx0 = min(max(x0, 0), Wl - 1);
    const int cx1 = min(max(x1, 0), Wl - 1);
    const int cy0 = min(max(y0, 0), Wl - 1);
    const int cy1 = min(max(y1, 0), Wl - 1);
    const int rb  = b * LIN + st;
    const int i00 = rb + cy0 * Wl + cx0;
    const int i01 = rb + cy0 * Wl + cx1;
    const int i10 = rb + cy1 * Wl + cx0;
    const int i11 = rb + cy1 * Wl + cx1;
    const float w00 = wa * (1.f - lx) * (1.f - ly) * (float)(vx0 && vy0);
    const float w01 = wa * lx         * (1.f - ly) * (float)(vx1 && vy0);
    const float w10 = wa * (1.f - lx) * ly         * (float)(vx0 && vy1);
    const float w11 = wa * lx         * ly         * (float)(vx1 && vy1);

    const float* __restrict__ vp = g_value + h * 32 + lane;  // channel = lane
    float acc = 0.f;
#pragma unroll
    for (int t = 0; t < 16; t++) {
        const float a0 = __shfl_sync(~0u, w00, t);
        const float a1 = __shfl_sync(~0u, w01, t);
        const float a2 = __shfl_sync(~0u, w10, t);
        const float a3 = __shfl_sync(~0u, w11, t);
        const int   j0 = __shfl_sync(~0u, i00, t);
        const int   j1 = __shfl_sync(~0u, i01, t);
        const int   j2 = __shfl_sync(~0u, i10, t);
        const int   j3 = __shfl_sync(~0u, i11, t);
        acc += a0 * vp[(size_t)j0 * 256];
        acc += a1 * vp[(size_t)j1 * 256];
        acc += a2 * vp[(size_t)j2 * 256];
        acc += a3 * vp[(size_t)j3 * 256];
    }
    g_core[row * 256 + h * 32 + lane] = acc;
}

// ---------------------------------------------------------------------------
extern "C" void kernel_launch(void* const* d_in, const int* in_sizes, int n_in,
                              void* d_out, int out_size)
{
    const float* query  = (const float*)d_in[0];
    const float* refp   = (const float*)d_in[1];
    const float* inpf   = (const float*)d_in[2];
    // d_in[3] spatial shapes, d_in[4] level starts: compile-time constants here
    const float* W_val  = (const float*)d_in[5];
    const float* b_val  = (const float*)d_in[6];
    const float* W_off  = (const float*)d_in[7];
    const float* b_off  = (const float*)d_in[8];
    const float* W_attn = (const float*)d_in[9];
    const float* b_attn = (const float*)d_in[10];
    const float* W_out  = (const float*)d_in[11];
    const float* b_out  = (const float*)d_in[12];
    float* out = (float*)d_out;

    float *p_val, *p_off, *p_attn, *p_core;
    cudaGetSymbolAddress((void**)&p_val,  g_value);
    cudaGetSymbolAddress((void**)&p_off,  g_off);
    cudaGetSymbolAddress((void**)&p_attn, g_attn);
    cudaGetSymbolAddress((void**)&p_core, g_core);

    dim3 g2(2, MTOT / 128);   // N=256
    dim3 g1(1, MTOT / 128);   // N=128

    sgemm_bias<<<g2, 256>>>(inpf,  W_val,  b_val,  p_val,  256, DM);
    sgemm_bias<<<g2, 256>>>(query, W_off,  b_off,  p_off,  256, DM);
    sgemm_bias<<<g1, 256>>>(query, W_attn, b_attn, p_attn, 128, DM);

    // one warp per (b,q,head): BB*LQ*NH warps, 8 warps/block
    msda_sample<<<(MTOT * NH) / 8, 256>>>(refp);

    sgemm_bias<<<g2, 256>>>(p_core, W_out, b_out, out, 256, DM);
}

// round 3
// speedup vs baseline: 1.7244x; 1.7244x over previous
#include <cuda_runtime.h>
#include <cuda_bf16.h>
#include <cstdint>

// Problem constants (fixed by the dataset)
#define BB   8
#define LQ   5440
#define LIN  5440
#define DM   256
#define NH   8
#define MTOT (BB * LQ)   // 43520

// ---------------------------------------------------------------------------
// Scratch (device globals; allocation-free per harness rules)
// ---------------------------------------------------------------------------
__device__ __align__(16) float g_value[MTOT * DM];
__device__ __align__(16) float g_off  [MTOT * DM];
__device__ __align__(16) float g_attn [MTOT * 128];
__device__ __align__(16) float g_core [MTOT * DM];

// Pre-split / pre-transposed weights, chunk-contiguous bf16 layout:
// element index = ((k>>6)*N + n)*64 + (k&63)   (64-wide K chunks, 128B rows)
__device__ __align__(16) __nv_bfloat16 g_wv_hi[DM * DM], g_wv_lo[DM * DM];
__device__ __align__(16) __nv_bfloat16 g_wo_hi[DM * DM], g_wo_lo[DM * DM];
__device__ __align__(16) __nv_bfloat16 g_wa_hi[DM * 128], g_wa_lo[DM * 128];
__device__ __align__(16) __nv_bfloat16 g_wu_hi[DM * DM], g_wu_lo[DM * DM];

// ---------------------------------------------------------------------------
// Helpers (base-target ISA only: ldmatrix / cp.async / mma.sync)
// ---------------------------------------------------------------------------
__device__ __forceinline__ uint32_t smem_u32(const void* p) {
    uint32_t a;
    asm("{ .reg .u64 t; cvta.to.shared.u64 t, %1; cvt.u32.u64 %0, t; }"
        : "=r"(a) : "l"(p));
    return a;
}
__device__ __forceinline__ void ldsm4(uint32_t* d, uint32_t addr) {
    asm volatile("ldmatrix.sync.aligned.m8n8.x4.shared.b16 {%0,%1,%2,%3}, [%4];"
                 : "=r"(d[0]), "=r"(d[1]), "=r"(d[2]), "=r"(d[3]) : "r"(addr));
}
__device__ __forceinline__ void mma16816(float* c, const uint32_t* a,
                                         const uint32_t* b) {
    asm volatile(
        "mma.sync.aligned.m16n8k16.row.col.f32.bf16.bf16.f32 "
        "{%0,%1,%2,%3}, {%4,%5,%6,%7}, {%8,%9}, {%0,%1,%2,%3};"
        : "+f"(c[0]), "+f"(c[1]), "+f"(c[2]), "+f"(c[3])
        : "r"(a[0]), "r"(a[1]), "r"(a[2]), "r"(a[3]), "r"(b[0]), "r"(b[1]));
}
__device__ __forceinline__ void cp16(uint32_t dst, const void* src) {
    asm volatile("cp.async.cg.shared.global [%0], [%1], 16;"
                 :: "r"(dst), "l"(src) : "memory");
}
__device__ __forceinline__ uint32_t sw128(uint32_t b) { return b ^ ((b >> 3) & 0x70); }

// ---------------------------------------------------------------------------
// Weight prep: fp32 W[K=256][N] -> transposed, bf16 hi/lo split, chunk layout
// ---------------------------------------------------------------------------
__global__ void prep_w(const float* __restrict__ W,
                       __nv_bfloat16* __restrict__ hi,
                       __nv_bfloat16* __restrict__ lo, int N)
{
    int idx = blockIdx.x * 256 + threadIdx.x;
    if (idx >= 256 * N) return;
    int k = idx / N, n = idx - k * N;
    float v = W[idx];
    __nv_bfloat16 h = __float2bfloat16(v);
    __nv_bfloat16 l = __float2bfloat16(v - __bfloat162float(h));
    int o = ((k >> 6) * N + n) * 64 + (k & 63);
    hi[o] = h; lo[o] = l;
}

// ---------------------------------------------------------------------------
// mma.sync bf16 GEMM, 3-term split: C[M,N] = A[M,256]*W + bias (fp32-grade).
// CTA: 128x128 tile, 256 thr (8 warps; warp tile 32x64). K: 4 chunks of 64,
// double-buffered smem. A converted in-kernel; B streamed via cp.async.
// SMEM per buffer: Ah,Al,Bh,Bl each 128x64 bf16 (16KB) -> 64KB; x2 = 128KB.
// ---------------------------------------------------------------------------
template <int N>
__global__ __launch_bounds__(256, 1) void gemm_mma(
    const float* __restrict__ A,
    const __nv_bfloat16* __restrict__ Bh_g, const __nv_bfloat16* __restrict__ Bl_g,
    const float* __restrict__ bias, float* __restrict__ C)
{
    extern __shared__ char smem[];
    constexpr int BUF = 65536;
    constexpr int O_AL = 16384, O_BH = 32768, O_BL = 49152;

    const int tid  = threadIdx.x;
    const int wid  = tid >> 5;
    const int lane = tid & 31;
    const int mBase = blockIdx.y * 128;
    const int nBase = blockIdx.x * 128;
    const int warpM = (wid & 3) * 32;      // 0,32,64,96
    const int warpN = (wid >> 2) * 64;     // 0,64

    const float4* Ag  = (const float4*)A;
    const uint4*  Bhg = (const uint4*)Bh_g;
    const uint4*  Blg = (const uint4*)Bl_g;

    float acc[2][8][4];
#pragma unroll
    for (int i = 0; i < 2; i++)
#pragma unroll
        for (int j = 0; j < 8; j++)
#pragma unroll
            for (int k = 0; k < 4; k++) acc[i][j][k] = 0.f;

    // ---- B chunk stream (cp.async), A chunk prefetch (registers) ----
    auto loadB = [&](int c, char* buf) {
        uint32_t bh = smem_u32(buf + O_BH), bl = smem_u32(buf + O_BL);
#pragma unroll
        for (int i = 0; i < 4; i++) {
            int f = tid + 256 * i;              // 0..1023 uint4 per split
            int n = f >> 3, u = f & 7;
            uint32_t so = (n << 7) + (((u ^ (n & 7))) << 4);
            size_t gi = (size_t)(c * N + nBase + n) * 8 + u;
            cp16(bh + so, Bhg + gi);
            cp16(bl + so, Blg + gi);
        }
        asm volatile("cp.async.commit_group;" ::: "memory");
    };

    float4 apf[8];
    auto loadA = [&](int c) {
#pragma unroll
        for (int i = 0; i < 8; i++) {
            int f = tid + 256 * i;              // 0..2047 float4
            int row = f >> 4, q = f & 15;
            apf[i] = Ag[(size_t)(mBase + row) * 64 + c * 16 + q];
        }
    };
    auto storeA = [&](char* buf) {
        char* ah = buf;
        char* al = buf + O_AL;
#pragma unroll
        for (int i = 0; i < 8; i++) {
            int f = tid + 256 * i;
            int row = f >> 4, q = f & 15;
            float4 v = apf[i];
            __nv_bfloat162 h0 = __floats2bfloat162_rn(v.x, v.y);
            __nv_bfloat162 h1 = __floats2bfloat162_rn(v.z, v.w);
            float2 f0 = __bfloat1622float2(h0), f1 = __bfloat1622float2(h1);
            __nv_bfloat162 l0 = __floats2bfloat162_rn(v.x - f0.x, v.y - f0.y);
            __nv_bfloat162 l1 = __floats2bfloat162_rn(v.z - f1.x, v.w - f1.y);
            uint32_t so = sw128(row * 128 + q * 8);
            *(__nv_bfloat162*)(ah + so)     = h0;
            *(__nv_bfloat162*)(ah + so + 4) = h1;
            *(__nv_bfloat162*)(al + so)     = l0;
            *(__nv_bfloat162*)(al + so + 4) = l1;
        }
    };

    loadB(0, smem);
    loadA(0);

    for (int c = 0; c < 4; c++) {
        char* buf = smem + (c & 1) * BUF;
        storeA(buf);
        if (c < 3) loadB(c + 1, smem + ((c + 1) & 1) * BUF);
        if (c < 3) asm volatile("cp.async.wait_group 1;" ::: "memory");
        else       asm volatile("cp.async.wait_group 0;" ::: "memory");
        __syncthreads();
        if (c < 3) loadA(c + 1);   // global loads overlap with compute below

        const uint32_t Ah = smem_u32(buf);
        const uint32_t Al = Ah + O_AL;
        const uint32_t Bh = Ah + O_BH;
        const uint32_t Bl = Ah + O_BL;

#pragma unroll
        for (int kk = 0; kk < 4; kk++) {
            uint32_t ah[2][4], al[2][4];
#pragma unroll
            for (int mi = 0; mi < 2; mi++) {
                int r = warpM + mi * 16 + (lane & 15);
                int u = kk * 2 + (lane >> 4);
                uint32_t off = (r << 7) + (((u ^ (r & 7))) << 4);
                ldsm4(ah[mi], Ah + off);
                ldsm4(al[mi], Al + off);
            }
#pragma unroll
            for (int half = 0; half < 2; half++) {
                uint32_t bh[4][2], bl[4][2];
#pragma unroll
                for (int p = 0; p < 2; p++) {
                    int r = warpN + (half * 4 + p * 2) * 8 +
                            ((lane >> 4) << 3) + (lane & 7);
                    int u = kk * 2 + ((lane >> 3) & 1);
                    uint32_t off = (r << 7) + (((u ^ (r & 7))) << 4);
                    ldsm4(&bh[p * 2][0], Bh + off);
                    ldsm4(&bl[p * 2][0], Bl + off);
                }
#pragma unroll
                for (int mi = 0; mi < 2; mi++)
#pragma unroll
                    for (int j = 0; j < 4; j++) {
                        float* cc = acc[mi][half * 4 + j];
                        mma16816(cc, ah[mi], bh[j]);
                        mma16816(cc, ah[mi], bl[j]);
                        mma16816(cc, al[mi], bh[j]);
                    }
            }
        }
        __syncthreads();
    }

    // ---- epilogue: bias + store ----
#pragma unroll
    for (int mi = 0; mi < 2; mi++) {
        int row0 = mBase + warpM + mi * 16 + (lane >> 2);
#pragma unroll
        for (int nj = 0; nj < 8; nj++) {
            int col = nBase + warpN + nj * 8 + (lane & 3) * 2;
            float bx = __ldg(bias + col), by = __ldg(bias + col + 1);
            float2 o0 = { acc[mi][nj][0] + bx, acc[mi][nj][1] + by };
            float2 o1 = { acc[mi][nj][2] + bx, acc[mi][nj][3] + by };
            *(float2*)(C + (size_t)row0 * N + col)       = o0;
            *(float2*)(C + (size_t)(row0 + 8) * N + col) = o1;
        }
    }
}

// ---------------------------------------------------------------------------
// Fused softmax + multi-scale deformable sampling (one warp per (b,q,head))
// ---------------------------------------------------------------------------
__global__ void msda_sample(const float* __restrict__ refp)
{
    const int gw   = (blockIdx.x * blockDim.x + threadIdx.x) >> 5;
    const int lane = threadIdx.x & 31;
    const int h    = gw & 7;
    const int row  = gw >> 3;          // b*LQ + q
    const int b    = row / LQ;

    const int s   = lane & 15;
    const int lvl = s >> 2;
    const int pt  = s & 3;
    const int Wl  = 64 >> lvl;
    const int st  = (16384 - (16384 >> (2 * lvl))) / 3;

    const float refx = refp[row * 8 + lvl * 2 + 0];
    const float refy = refp[row * 8 + lvl * 2 + 1];
    const int obase  = row * 256 + (((h * 4 + lvl) * 4 + pt) * 2);
    const float offx = g_off[obase + 0];
    const float offy = g_off[obase + 1];

    const float x = refx * (float)Wl + offx - 0.5f;
    const float y = refy * (float)Wl + offy - 0.5f;
    const float fx = floorf(x), fy = floorf(y);
    const float lx = x - fx,   ly = y - fy;
    const int x0 = (int)fx, y0 = (int)fy;
    const int x1 = x0 + 1,  y1 = y0 + 1;

    const float logit = g_attn[row * 128 + h * 16 + s];
    float mx = logit;
#pragma unroll
    for (int o = 8; o; o >>= 1) mx = fmaxf(mx, __shfl_xor_sync(~0u, mx, o, 16));
    const float e = __expf(logit - mx);
    float sum = e;
#pragma unroll
    for (int o = 8; o; o >>= 1) sum += __shfl_xor_sync(~0u, sum, o, 16);
    const float wa = e / sum;

    const bool vx0 = (unsigned)x0 < (unsigned)Wl;
    const bool vx1 = (unsigned)x1 < (unsigned)Wl;
    const bool vy0 = (unsigned)y0 < (unsigned)Wl;
    const bool vy1 = (unsigned)y1 < (unsigned)Wl;
    const int cx0 = min(max(x0, 0), Wl - 1);
    const int cx1 = min(max(x1, 0), Wl - 1);
    const int cy0 = min(max(y0, 0), Wl - 1);
    const int cy1 = min(max(y1, 0), Wl - 1);
    const int rb  = b * LIN + st;
    const int i00 = rb + cy0 * Wl + cx0;
    const int i01 = rb + cy0 * Wl + cx1;
    const int i10 = rb + cy1 * Wl + cx0;
    const int i11 = rb + cy1 * Wl + cx1;
    const float w00 = wa * (1.f - lx) * (1.f - ly) * (float)(vx0 && vy0);
    const float w01 = wa * lx         * (1.f - ly) * (float)(vx1 && vy0);
    const float w10 = wa * (1.f - lx) * ly         * (float)(vx0 && vy1);
    const float w11 = wa * lx         * ly         * (float)(vx1 && vy1);

    const float* __restrict__ vp = g_value + h * 32 + lane;
    float a0 = 0.f, a1 = 0.f, a2 = 0.f, a3 = 0.f;
#pragma unroll
    for (int t = 0; t < 16; t++) {
        const float c0 = __shfl_sync(~0u, w00, t);
        const float c1 = __shfl_sync(~0u, w01, t);
        const float c2 = __shfl_sync(~0u, w10, t);
        const float c3 = __shfl_sync(~0u, w11, t);
        const int   j0 = __shfl_sync(~0u, i00, t);
        const int   j1 = __shfl_sync(~0u, i01, t);
        const int   j2 = __shfl_sync(~0u, i10, t);
        const int   j3 = __shfl_sync(~0u, i11, t);
        a0 += c0 * vp[(size_t)j0 * 256];
        a1 += c1 * vp[(size_t)j1 * 256];
        a2 += c2 * vp[(size_t)j2 * 256];
        a3 += c3 * vp[(size_t)j3 * 256];
    }
    g_core[row * 256 + h * 32 + lane] = (a0 + a1) + (a2 + a3);
}

// ---------------------------------------------------------------------------
extern "C" void kernel_launch(void* const* d_in, const int* in_sizes, int n_in,
                              void* d_out, int out_size)
{
    const float* query  = (const float*)d_in[0];
    const float* refp   = (const float*)d_in[1];
    const float* inpf   = (const float*)d_in[2];
    const float* W_val  = (const float*)d_in[5];
    const float* b_val  = (const float*)d_in[6];
    const float* W_off  = (const float*)d_in[7];
    const float* b_off  = (const float*)d_in[8];
    const float* W_attn = (const float*)d_in[9];
    const float* b_attn = (const float*)d_in[10];
    const float* W_out  = (const float*)d_in[11];
    const float* b_out  = (const float*)d_in[12];
    float* out = (float*)d_out;

    float *p_val, *p_off, *p_attn, *p_core;
    cudaGetSymbolAddress((void**)&p_val,  g_value);
    cudaGetSymbolAddress((void**)&p_off,  g_off);
    cudaGetSymbolAddress((void**)&p_attn, g_attn);
    cudaGetSymbolAddress((void**)&p_core, g_core);
    __nv_bfloat16 *wv_h, *wv_l, *wo_h, *wo_l, *wa_h, *wa_l, *wu_h, *wu_l;
    cudaGetSymbolAddress((void**)&wv_h, g_wv_hi); cudaGetSymbolAddress((void**)&wv_l, g_wv_lo);
    cudaGetSymbolAddress((void**)&wo_h, g_wo_hi); cudaGetSymbolAddress((void**)&wo_l, g_wo_lo);
    cudaGetSymbolAddress((void**)&wa_h, g_wa_hi); cudaGetSymbolAddress((void**)&wa_l, g_wa_lo);
    cudaGetSymbolAddress((void**)&wu_h, g_wu_hi); cudaGetSymbolAddress((void**)&wu_l, g_wu_lo);

    constexpr int SMEM = 131072;
    cudaFuncSetAttribute(gemm_mma<256>, cudaFuncAttributeMaxDynamicSharedMemorySize, SMEM);
    cudaFuncSetAttribute(gemm_mma<128>, cudaFuncAttributeMaxDynamicSharedMemorySize, SMEM);

    // Weight prep (tiny)
    prep_w<<<256, 256>>>(W_val,  wv_h, wv_l, 256);
    prep_w<<<256, 256>>>(W_off,  wo_h, wo_l, 256);
    prep_w<<<128, 256>>>(W_attn, wa_h, wa_l, 128);
    prep_w<<<256, 256>>>(W_out,  wu_h, wu_l, 256);

    const int MT = MTOT / 128;  // 340
    gemm_mma<256><<<dim3(2, MT), 256, SMEM>>>(inpf,  wv_h, wv_l, b_val,  p_val);
    gemm_mma<256><<<dim3(2, MT), 256, SMEM>>>(query, wo_h, wo_l, b_off,  p_off);
    gemm_mma<128><<<dim3(1, MT), 256, SMEM>>>(query, wa_h, wa_l, b_attn, p_attn);

    msda_sample<<<(MTOT * NH) / 8, 256>>>(refp);

    gemm_mma<256><<<dim3(2, MT), 256, SMEM>>>(p_core, wu_h, wu_l, b_out, out);
}

// round 4
// speedup vs baseline: 1.7803x; 1.0324x over previous
#include <cuda_runtime.h>
#include <cuda_bf16.h>
#include <cuda_fp16.h>
#include <cstdint>

// Problem constants (fixed by the dataset)
#define BB   8
#define LQ   5440
#define LIN  5440
#define DM   256
#define NH   8
#define MTOT (BB * LQ)   // 43520

// ---------------------------------------------------------------------------
// Scratch (device globals; allocation-free per harness rules)
// ---------------------------------------------------------------------------
__device__ __align__(16) __half g_value_h[MTOT * DM];       // fp16 value
__device__ __align__(16) float  g_oa  [MTOT * 384];         // off(256) + attn logits(128)
__device__ __align__(16) float  g_core[MTOT * DM];

// Pre-split / pre-transposed weights, chunk-contiguous bf16 layout:
// element index = ((k>>6)*N + n)*64 + (k&63)   (64-wide K chunks)
__device__ __align__(16) __nv_bfloat16 g_wv_hi [DM * DM],  g_wv_lo [DM * DM];
__device__ __align__(16) __nv_bfloat16 g_woa_hi[DM * 384], g_woa_lo[DM * 384];
__device__ __align__(16) __nv_bfloat16 g_wu_hi [DM * DM],  g_wu_lo [DM * DM];
__device__ __align__(16) float g_boa[384];

// ---------------------------------------------------------------------------
// Helpers (base-target ISA only: ldmatrix / cp.async / mma.sync)
// ---------------------------------------------------------------------------
__device__ __forceinline__ uint32_t smem_u32(const void* p) {
    uint32_t a;
    asm("{ .reg .u64 t; cvta.to.shared.u64 t, %1; cvt.u32.u64 %0, t; }"
        : "=r"(a) : "l"(p));
    return a;
}
__device__ __forceinline__ void ldsm4(uint32_t* d, uint32_t addr) {
    asm volatile("ldmatrix.sync.aligned.m8n8.x4.shared.b16 {%0,%1,%2,%3}, [%4];"
                 : "=r"(d[0]), "=r"(d[1]), "=r"(d[2]), "=r"(d[3]) : "r"(addr));
}
__device__ __forceinline__ void mma16816(float* c, const uint32_t* a,
                                         const uint32_t* b) {
    asm volatile(
        "mma.sync.aligned.m16n8k16.row.col.f32.bf16.bf16.f32 "
        "{%0,%1,%2,%3}, {%4,%5,%6,%7}, {%8,%9}, {%0,%1,%2,%3};"
        : "+f"(c[0]), "+f"(c[1]), "+f"(c[2]), "+f"(c[3])
        : "r"(a[0]), "r"(a[1]), "r"(a[2]), "r"(a[3]), "r"(b[0]), "r"(b[1]));
}
__device__ __forceinline__ void cp16(uint32_t dst, const void* src) {
    asm volatile("cp.async.cg.shared.global [%0], [%1], 16;"
                 :: "r"(dst), "l"(src) : "memory");
}
__device__ __forceinline__ uint32_t sw128(uint32_t b) { return b ^ ((b >> 3) & 0x70); }

// ---------------------------------------------------------------------------
// Fused weight prep: all three weight matrices (val / off+attn combined / out)
// transposed + bf16 hi/lo split into chunk-contiguous layout, plus combined bias.
// ---------------------------------------------------------------------------
__global__ void prep_all(const float* __restrict__ W_val,
                         const float* __restrict__ W_off,
                         const float* __restrict__ W_attn,
                         const float* __restrict__ W_out,
                         const float* __restrict__ b_off,
                         const float* __restrict__ b_attn)
{
    __nv_bfloat16 *wv_h = g_wv_hi,  *wv_l = g_wv_lo;
    __nv_bfloat16 *wa_h = g_woa_hi, *wa_l = g_woa_lo;
    __nv_bfloat16 *wu_h = g_wu_hi,  *wu_l = g_wu_lo;

    int idx = blockIdx.x * 256 + threadIdx.x;
    if (idx < 384)
        g_boa[idx] = idx < 256 ? b_off[idx] : b_attn[idx - 256];

    float v; __nv_bfloat16 *hi, *lo; int o;
    if (idx < 65536) {                       // W_val [256x256]
        int k = idx >> 8, n = idx & 255;
        v = W_val[idx];
        o = (((k >> 6) << 8) + n) * 64 + (k & 63);
        hi = wv_h; lo = wv_l;
    } else if (idx < 65536 + 98304) {        // combined [256x384]
        int t = idx - 65536;
        int k = t / 384, n = t - k * 384;
        v = n < 256 ? W_off[k * 256 + n] : W_attn[k * 128 + (n - 256)];
        o = ((k >> 6) * 384 + n) * 64 + (k & 63);
        hi = wa_h; lo = wa_l;
    } else {                                 // W_out [256x256]
        int t = idx - 65536 - 98304;
        int k = t >> 8, n = t & 255;
        v = W_out[t];
        o = (((k >> 6) << 8) + n) * 64 + (k & 63);
        hi = wu_h; lo = wu_l;
    }
    __nv_bfloat16 h = __float2bfloat16(v);
    hi[o] = h;
    lo[o] = __float2bfloat16(v - __bfloat162float(h));
}

// ---------------------------------------------------------------------------
// mma.sync bf16 GEMM, 3-term split: C[M,N] = A[M,256]*W + bias (fp32-grade).
// CTA: 128x128 tile, 256 thr (8 warps; warp tile 32x64). K: 4 chunks of 64,
// double-buffered smem. OutT selects fp32 or fp16 output.
// ---------------------------------------------------------------------------
template <int N, typename OutT>
__global__ __launch_bounds__(256, 1) void gemm_mma(
    const float* __restrict__ A,
    const __nv_bfloat16* __restrict__ Bh_g, const __nv_bfloat16* __restrict__ Bl_g,
    const float* __restrict__ bias, OutT* __restrict__ C)
{
    extern __shared__ char smem[];
    constexpr int BUF = 65536;
    constexpr int O_AL = 16384, O_BH = 32768, O_BL = 49152;

    const int tid  = threadIdx.x;
    const int wid  = tid >> 5;
    const int lane = tid & 31;
    const int mBase = blockIdx.y * 128;
    const int nBase = blockIdx.x * 128;
    const int warpM = (wid & 3) * 32;
    const int warpN = (wid >> 2) * 64;

    const float4* Ag  = (const float4*)A;
    const uint4*  Bhg = (const uint4*)Bh_g;
    const uint4*  Blg = (const uint4*)Bl_g;

    float acc[2][8][4];
#pragma unroll
    for (int i = 0; i < 2; i++)
#pragma unroll
        for (int j = 0; j < 8; j++)
#pragma unroll
            for (int k = 0; k < 4; k++) acc[i][j][k] = 0.f;

    auto loadB = [&](int c, char* buf) {
        uint32_t bh = smem_u32(buf + O_BH), bl = smem_u32(buf + O_BL);
#pragma unroll
        for (int i = 0; i < 4; i++) {
            int f = tid + 256 * i;
            int n = f >> 3, u = f & 7;
            uint32_t so = (n << 7) + (((u ^ (n & 7))) << 4);
            size_t gi = (size_t)(c * N + nBase + n) * 8 + u;
            cp16(bh + so, Bhg + gi);
            cp16(bl + so, Blg + gi);
        }
        asm volatile("cp.async.commit_group;" ::: "memory");
    };

    float4 apf[8];
    auto loadA = [&](int c) {
#pragma unroll
        for (int i = 0; i < 8; i++) {
            int f = tid + 256 * i;
            int row = f >> 4, q = f & 15;
            apf[i] = Ag[(size_t)(mBase + row) * 64 + c * 16 + q];
        }
    };
    auto storeA = [&](char* buf) {
        char* ah = buf;
        char* al = buf + O_AL;
#pragma unroll
        for (int i = 0; i < 8; i++) {
            int f = tid + 256 * i;
            int row = f >> 4, q = f & 15;
            float4 v = apf[i];
            __nv_bfloat162 h0 = __floats2bfloat162_rn(v.x, v.y);
            __nv_bfloat162 h1 = __floats2bfloat162_rn(v.z, v.w);
            float2 f0 = __bfloat1622float2(h0), f1 = __bfloat1622float2(h1);
            __nv_bfloat162 l0 = __floats2bfloat162_rn(v.x - f0.x, v.y - f0.y);
            __nv_bfloat162 l1 = __floats2bfloat162_rn(v.z - f1.x, v.w - f1.y);
            uint32_t so = sw128(row * 128 + q * 8);
            *(__nv_bfloat162*)(ah + so)     = h0;
            *(__nv_bfloat162*)(ah + so + 4) = h1;
            *(__nv_bfloat162*)(al + so)     = l0;
            *(__nv_bfloat162*)(al + so + 4) = l1;
        }
    };

    loadB(0, smem);
    loadA(0);

    for (int c = 0; c < 4; c++) {
        char* buf = smem + (c & 1) * BUF;
        storeA(buf);
        if (c < 3) loadB(c + 1, smem + ((c + 1) & 1) * BUF);
        if (c < 3) asm volatile("cp.async.wait_group 1;" ::: "memory");
        else       asm volatile("cp.async.wait_group 0;" ::: "memory");
        __syncthreads();
        if (c < 3) loadA(c + 1);

        const uint32_t Ah = smem_u32(buf);
        const uint32_t Al = Ah + O_AL;
        const uint32_t Bh = Ah + O_BH;
        const uint32_t Bl = Ah + O_BL;

#pragma unroll
        for (int kk = 0; kk < 4; kk++) {
            uint32_t ah[2][4], al[2][4];
#pragma unroll
            for (int mi = 0; mi < 2; mi++) {
                int r = warpM + mi * 16 + (lane & 15);
                int u = kk * 2 + (lane >> 4);
                uint32_t off = (r << 7) + (((u ^ (r & 7))) << 4);
                ldsm4(ah[mi], Ah + off);
                ldsm4(al[mi], Al + off);
            }
#pragma unroll
            for (int half = 0; half < 2; half++) {
                uint32_t bh[4][2], bl[4][2];
#pragma unroll
                for (int p = 0; p < 2; p++) {
                    int r = warpN + (half * 4 + p * 2) * 8 +
                            ((lane >> 4) << 3) + (lane & 7);
                    int u = kk * 2 + ((lane >> 3) & 1);
                    uint32_t off = (r << 7) + (((u ^ (r & 7))) << 4);
                    ldsm4(&bh[p * 2][0], Bh + off);
                    ldsm4(&bl[p * 2][0], Bl + off);
                }
#pragma unroll
                for (int mi = 0; mi < 2; mi++)
#pragma unroll
                    for (int j = 0; j < 4; j++) {
                        float* cc = acc[mi][half * 4 + j];
                        mma16816(cc, ah[mi], bh[j]);
                        mma16816(cc, ah[mi], bl[j]);
                        mma16816(cc, al[mi], bh[j]);
                    }
            }
        }
        __syncthreads();
    }

    // ---- epilogue: bias + store (fp32 or fp16) ----
#pragma unroll
    for (int mi = 0; mi < 2; mi++) {
        int row0 = mBase + warpM + mi * 16 + (lane >> 2);
#pragma unroll
        for (int nj = 0; nj < 8; nj++) {
            int col = nBase + warpN + nj * 8 + (lane & 3) * 2;
            float bx = __ldg(bias + col), by = __ldg(bias + col + 1);
            float v00 = acc[mi][nj][0] + bx, v01 = acc[mi][nj][1] + by;
            float v10 = acc[mi][nj][2] + bx, v11 = acc[mi][nj][3] + by;
            if constexpr (sizeof(OutT) == 4) {
                *(float2*)((float*)C + (size_t)row0 * N + col)       = make_float2(v00, v01);
                *(float2*)((float*)C + (size_t)(row0 + 8) * N + col) = make_float2(v10, v11);
            } else {
                *(__half2*)((__half*)C + (size_t)row0 * N + col)       = __floats2half2_rn(v00, v01);
                *(__half2*)((__half*)C + (size_t)(row0 + 8) * N + col) = __floats2half2_rn(v10, v11);
            }
        }
    }
}

// ---------------------------------------------------------------------------
// Fused softmax + multi-scale deformable sampling (one warp per (b,q,head)).
// Value is fp16 -> 64B per warp-gather (half the L1 traffic of fp32).
// ---------------------------------------------------------------------------
__global__ void msda_sample(const float* __restrict__ refp)
{
    const int gw   = (blockIdx.x * blockDim.x + threadIdx.x) >> 5;
    const int lane = threadIdx.x & 31;
    const int h    = gw & 7;
    const int row  = gw >> 3;          // b*LQ + q
    const int b    = row / LQ;

    const int s   = lane & 15;
    const int lvl = s >> 2;
    const int pt  = s & 3;
    const int Wl  = 64 >> lvl;
    const int st  = (16384 - (16384 >> (2 * lvl))) / 3;

    const float refx = refp[row * 8 + lvl * 2 + 0];
    const float refy = refp[row * 8 + lvl * 2 + 1];
    const int obase  = row * 384 + (((h * 4 + lvl) * 4 + pt) * 2);
    const float offx = g_oa[obase + 0];
    const float offy = g_oa[obase + 1];

    const float x = refx * (float)Wl + offx - 0.5f;
    const float y = refy * (float)Wl + offy - 0.5f;
    const float fx = floorf(x), fy = floorf(y);
    const float lx = x - fx,   ly = y - fy;
    const int x0 = (int)fx, y0 = (int)fy;
    const int x1 = x0 + 1,  y1 = y0 + 1;

    const float logit = g_oa[row * 384 + 256 + h * 16 + s];
    float mx = logit;
#pragma unroll
    for (int o = 8; o; o >>= 1) mx = fmaxf(mx, __shfl_xor_sync(~0u, mx, o, 16));
    const float e = __expf(logit - mx);
    float sum = e;
#pragma unroll
    for (int o = 8; o; o >>= 1) sum += __shfl_xor_sync(~0u, sum, o, 16);
    const float wa = e / sum;

    const bool vx0 = (unsigned)x0 < (unsigned)Wl;
    const bool vx1 = (unsigned)x1 < (unsigned)Wl;
    const bool vy0 = (unsigned)y0 < (unsigned)Wl;
    const bool vy1 = (unsigned)y1 < (unsigned)Wl;
    const int cx0 = min(max(x0, 0), Wl - 1);
    const int cx1 = min(max(x1, 0), Wl - 1);
    const int cy0 = min(max(y0, 0), Wl - 1);
    const int cy1 = min(max(y1, 0), Wl - 1);
    const int rb  = b * LIN + st;
    const int i00 = rb + cy0 * Wl + cx0;
    const int i01 = rb + cy0 * Wl + cx1;
    const int i10 = rb + cy1 * Wl + cx0;
    const int i11 = rb + cy1 * Wl + cx1;
    const float w00 = wa * (1.f - lx) * (1.f - ly) * (float)(vx0 && vy0);
    const float w01 = wa * lx         * (1.f - ly) * (float)(vx1 && vy0);
    const float w10 = wa * (1.f - lx) * ly         * (float)(vx0 && vy1);
    const float w11 = wa * lx         * ly         * (float)(vx1 && vy1);

    const __half* __restrict__ vp = g_value_h + h * 32 + lane;
    float a0 = 0.f, a1 = 0.f, a2 = 0.f, a3 = 0.f;
#pragma unroll
    for (int t = 0; t < 16; t++) {
        const float c0 = __shfl_sync(~0u, w00, t);
        const float c1 = __shfl_sync(~0u, w01, t);
        const float c2 = __shfl_sync(~0u, w10, t);
        const float c3 = __shfl_sync(~0u, w11, t);
        const int   j0 = __shfl_sync(~0u, i00, t);
        const int   j1 = __shfl_sync(~0u, i01, t);
        const int   j2 = __shfl_sync(~0u, i10, t);
        const int   j3 = __shfl_sync(~0u, i11, t);
        a0 += c0 * __half2float(vp[(size_t)j0 * 256]);
        a1 += c1 * __half2float(vp[(size_t)j1 * 256]);
        a2 += c2 * __half2float(vp[(size_t)j2 * 256]);
        a3 += c3 * __half2float(vp[(size_t)j3 * 256]);
    }
    g_core[row * 256 + h * 32 + lane] = (a0 + a1) + (a2 + a3);
}

// ---------------------------------------------------------------------------
extern "C" void kernel_launch(void* const* d_in, const int* in_sizes, int n_in,
                              void* d_out, int out_size)
{
    const float* query  = (const float*)d_in[0];
    const float* refp   = (const float*)d_in[1];
    const float* inpf   = (const float*)d_in[2];
    const float* W_val  = (const float*)d_in[5];
    const float* b_val  = (const float*)d_in[6];
    const float* W_off  = (const float*)d_in[7];
    const float* b_attn = (const float*)d_in[10];
    const float* b_off  = (const float*)d_in[8];
    const float* W_attn = (const float*)d_in[9];
    const float* W_out  = (const float*)d_in[11];
    const float* b_out  = (const float*)d_in[12];
    float* out = (float*)d_out;

    __half* p_val;  float *p_oa, *p_core, *p_boa;
    cudaGetSymbolAddress((void**)&p_val,  g_value_h);
    cudaGetSymbolAddress((void**)&p_oa,   g_oa);
    cudaGetSymbolAddress((void**)&p_core, g_core);
    cudaGetSymbolAddress((void**)&p_boa,  g_boa);
    __nv_bfloat16 *wv_h, *wv_l, *woa_h, *woa_l, *wu_h, *wu_l;
    cudaGetSymbolAddress((void**)&wv_h,  g_wv_hi);  cudaGetSymbolAddress((void**)&wv_l,  g_wv_lo);
    cudaGetSymbolAddress((void**)&woa_h, g_woa_hi); cudaGetSymbolAddress((void**)&woa_l, g_woa_lo);
    cudaGetSymbolAddress((void**)&wu_h,  g_wu_hi);  cudaGetSymbolAddress((void**)&wu_l,  g_wu_lo);

    constexpr int SMEM = 131072;
    cudaFuncSetAttribute(gemm_mma<256, float>,  cudaFuncAttributeMaxDynamicSharedMemorySize, SMEM);
    cudaFuncSetAttribute(gemm_mma<256, __half>, cudaFuncAttributeMaxDynamicSharedMemorySize, SMEM);
    cudaFuncSetAttribute(gemm_mma<384, float>,  cudaFuncAttributeMaxDynamicSharedMemorySize, SMEM);

    // Fused weight prep: 229376 elements = 896 blocks x 256
    prep_all<<<896, 256>>>(W_val, W_off, W_attn, W_out, b_off, b_attn);

    const int MT = MTOT / 128;  // 340
    gemm_mma<256, __half><<<dim3(2, MT), 256, SMEM>>>(inpf,  wv_h,  wv_l,  b_val, p_val);
    gemm_mma<384, float ><<<dim3(3, MT), 256, SMEM>>>(query, woa_h, woa_l, p_boa, p_oa);

    msda_sample<<<(MTOT * NH) / 8, 256>>>(refp);

    gemm_mma<256, float ><<<dim3(2, MT), 256, SMEM>>>(p_core, wu_h, wu_l, b_out, out);
}

// round 5
// speedup vs baseline: 2.4625x; 1.3832x over previous
#include <cuda_runtime.h>
#include <cuda_bf16.h>
#include <cuda_fp16.h>
#include <cstdint>

// Problem constants (fixed by the dataset)
#define BB   8
#define LQ   5440
#define LIN  5440
#define DM   256
#define NH   8
#define MTOT (BB * LQ)   // 43520

// ---------------------------------------------------------------------------
// Scratch (device globals; allocation-free per harness rules)
// ---------------------------------------------------------------------------
__device__ __align__(16) __half g_value_h[MTOT * DM];       // fp16 value
__device__ __align__(16) float  g_oa  [MTOT * 384];         // off(256) + attn logits(128)
__device__ __align__(16) float  g_core[MTOT * DM];

// Pre-split / pre-transposed weights, chunk-contiguous bf16 layout:
// element index = ((k>>6)*N + n)*64 + (k&63)   (64-wide K chunks)
__device__ __align__(16) __nv_bfloat16 g_wv_hi [DM * DM],  g_wv_lo [DM * DM];
__device__ __align__(16) __nv_bfloat16 g_woa_hi[DM * 384], g_woa_lo[DM * 384];
__device__ __align__(16) __nv_bfloat16 g_wu_hi [DM * DM],  g_wu_lo [DM * DM];
__device__ __align__(16) float g_boa[384];

// ---------------------------------------------------------------------------
// Helpers (base-target ISA only: ldmatrix / cp.async / mma.sync)
// ---------------------------------------------------------------------------
__device__ __forceinline__ uint32_t smem_u32(const void* p) {
    uint32_t a;
    asm("{ .reg .u64 t; cvta.to.shared.u64 t, %1; cvt.u32.u64 %0, t; }"
        : "=r"(a) : "l"(p));
    return a;
}
__device__ __forceinline__ void ldsm4(uint32_t* d, uint32_t addr) {
    asm volatile("ldmatrix.sync.aligned.m8n8.x4.shared.b16 {%0,%1,%2,%3}, [%4];"
                 : "=r"(d[0]), "=r"(d[1]), "=r"(d[2]), "=r"(d[3]) : "r"(addr));
}
__device__ __forceinline__ void mma16816(float* c, const uint32_t* a,
                                         const uint32_t* b) {
    asm volatile(
        "mma.sync.aligned.m16n8k16.row.col.f32.bf16.bf16.f32 "
        "{%0,%1,%2,%3}, {%4,%5,%6,%7}, {%8,%9}, {%0,%1,%2,%3};"
        : "+f"(c[0]), "+f"(c[1]), "+f"(c[2]), "+f"(c[3])
        : "r"(a[0]), "r"(a[1]), "r"(a[2]), "r"(a[3]), "r"(b[0]), "r"(b[1]));
}
__device__ __forceinline__ void cp16(uint32_t dst, const void* src) {
    asm volatile("cp.async.cg.shared.global [%0], [%1], 16;"
                 :: "r"(dst), "l"(src) : "memory");
}
__device__ __forceinline__ uint32_t sw128(uint32_t b) { return b ^ ((b >> 3) & 0x70); }

// ---------------------------------------------------------------------------
// Fused weight prep: all three weight matrices (val / off+attn combined / out)
// transposed + bf16 hi/lo split into chunk-contiguous layout, plus combined bias.
// ---------------------------------------------------------------------------
__global__ void prep_all(const float* __restrict__ W_val,
                         const float* __restrict__ W_off,
                         const float* __restrict__ W_attn,
                         const float* __restrict__ W_out,
                         const float* __restrict__ b_off,
                         const float* __restrict__ b_attn)
{
    __nv_bfloat16 *wv_h = g_wv_hi,  *wv_l = g_wv_lo;
    __nv_bfloat16 *wa_h = g_woa_hi, *wa_l = g_woa_lo;
    __nv_bfloat16 *wu_h = g_wu_hi,  *wu_l = g_wu_lo;

    int idx = blockIdx.x * 256 + threadIdx.x;
    if (idx < 384)
        g_boa[idx] = idx < 256 ? b_off[idx] : b_attn[idx - 256];

    float v; __nv_bfloat16 *hi, *lo; int o;
    if (idx < 65536) {                       // W_val [256x256]
        int k = idx >> 8, n = idx & 255;
        v = W_val[idx];
        o = (((k >> 6) << 8) + n) * 64 + (k & 63);
        hi = wv_h; lo = wv_l;
    } else if (idx < 65536 + 98304) {        // combined [256x384]
        int t = idx - 65536;
        int k = t / 384, n = t - k * 384;
        v = n < 256 ? W_off[k * 256 + n] : W_attn[k * 128 + (n - 256)];
        o = ((k >> 6) * 384 + n) * 64 + (k & 63);
        hi = wa_h; lo = wa_l;
    } else {                                 // W_out [256x256]
        int t = idx - 65536 - 98304;
        int k = t >> 8, n = t & 255;
        v = W_out[t];
        o = (((k >> 6) << 8) + n) * 64 + (k & 63);
        hi = wu_h; lo = wu_l;
    }
    __nv_bfloat16 h = __float2bfloat16(v);
    hi[o] = h;
    lo[o] = __float2bfloat16(v - __bfloat162float(h));
}

// ---------------------------------------------------------------------------
// mma.sync bf16 GEMM, 3-term split: C[M,N] = A[M,256]*W + bias (fp32-grade).
// CTA: 128x128 tile, 256 thr (8 warps; warp tile 32x64). K: 4 chunks of 64,
// double-buffered smem. OutT selects fp32 or fp16 output.
// ---------------------------------------------------------------------------
template <int N, typename OutT>
__global__ __launch_bounds__(256, 1) void gemm_mma(
    const float* __restrict__ A,
    const __nv_bfloat16* __restrict__ Bh_g, const __nv_bfloat16* __restrict__ Bl_g,
    const float* __restrict__ bias, OutT* __restrict__ C)
{
    extern __shared__ char smem[];
    constexpr int BUF = 65536;
    constexpr int O_AL = 16384, O_BH = 32768, O_BL = 49152;

    const int tid  = threadIdx.x;
    const int wid  = tid >> 5;
    const int lane = tid & 31;
    const int mBase = blockIdx.y * 128;
    const int nBase = blockIdx.x * 128;
    const int warpM = (wid & 3) * 32;
    const int warpN = (wid >> 2) * 64;

    const float4* Ag  = (const float4*)A;
    const uint4*  Bhg = (const uint4*)Bh_g;
    const uint4*  Blg = (const uint4*)Bl_g;

    float acc[2][8][4];
#pragma unroll
    for (int i = 0; i < 2; i++)
#pragma unroll
        for (int j = 0; j < 8; j++)
#pragma unroll
            for (int k = 0; k < 4; k++) acc[i][j][k] = 0.f;

    auto loadB = [&](int c, char* buf) {
        uint32_t bh = smem_u32(buf + O_BH), bl = smem_u32(buf + O_BL);
#pragma unroll
        for (int i = 0; i < 4; i++) {
            int f = tid + 256 * i;
            int n = f >> 3, u = f & 7;
            uint32_t so = (n << 7) + (((u ^ (n & 7))) << 4);
            size_t gi = (size_t)(c * N + nBase + n) * 8 + u;
            cp16(bh + so, Bhg + gi);
            cp16(bl + so, Blg + gi);
        }
        asm volatile("cp.async.commit_group;" ::: "memory");
    };

    float4 apf[8];
    auto loadA = [&](int c) {
#pragma unroll
        for (int i = 0; i < 8; i++) {
            int f = tid + 256 * i;
            int row = f >> 4, q = f & 15;
            apf[i] = Ag[(size_t)(mBase + row) * 64 + c * 16 + q];
        }
    };
    auto storeA = [&](char* buf) {
        char* ah = buf;
        char* al = buf + O_AL;
#pragma unroll
        for (int i = 0; i < 8; i++) {
            int f = tid + 256 * i;
            int row = f >> 4, q = f & 15;
            float4 v = apf[i];
            __nv_bfloat162 h0 = __floats2bfloat162_rn(v.x, v.y);
            __nv_bfloat162 h1 = __floats2bfloat162_rn(v.z, v.w);
            float2 f0 = __bfloat1622float2(h0), f1 = __bfloat1622float2(h1);
            __nv_bfloat162 l0 = __floats2bfloat162_rn(v.x - f0.x, v.y - f0.y);
            __nv_bfloat162 l1 = __floats2bfloat162_rn(v.z - f1.x, v.w - f1.y);
            uint32_t so = sw128(row * 128 + q * 8);
            *(__nv_bfloat162*)(ah + so)     = h0;
            *(__nv_bfloat162*)(ah + so + 4) = h1;
            *(__nv_bfloat162*)(al + so)     = l0;
            *(__nv_bfloat162*)(al + so + 4) = l1;
        }
    };

    loadB(0, smem);
    loadA(0);

    for (int c = 0; c < 4; c++) {
        char* buf = smem + (c & 1) * BUF;
        storeA(buf);
        if (c < 3) loadB(c + 1, smem + ((c + 1) & 1) * BUF);
        if (c < 3) asm volatile("cp.async.wait_group 1;" ::: "memory");
        else       asm volatile("cp.async.wait_group 0;" ::: "memory");
        __syncthreads();
        if (c < 3) loadA(c + 1);

        const uint32_t Ah = smem_u32(buf);
        const uint32_t Al = Ah + O_AL;
        const uint32_t Bh = Ah + O_BH;
        const uint32_t Bl = Ah + O_BL;

#pragma unroll
        for (int kk = 0; kk < 4; kk++) {
            uint32_t ah[2][4], al[2][4];
#pragma unroll
            for (int mi = 0; mi < 2; mi++) {
                int r = warpM + mi * 16 + (lane & 15);
                int u = kk * 2 + (lane >> 4);
                uint32_t off = (r << 7) + (((u ^ (r & 7))) << 4);
                ldsm4(ah[mi], Ah + off);
                ldsm4(al[mi], Al + off);
            }
#pragma unroll
            for (int half = 0; half < 2; half++) {
                uint32_t bh[4][2], bl[4][2];
#pragma unroll
                for (int p = 0; p < 2; p++) {
                    int r = warpN + (half * 4 + p * 2) * 8 +
                            ((lane >> 4) << 3) + (lane & 7);
                    int u = kk * 2 + ((lane >> 3) & 1);
                    uint32_t off = (r << 7) + (((u ^ (r & 7))) << 4);
                    ldsm4(&bh[p * 2][0], Bh + off);
                    ldsm4(&bl[p * 2][0], Bl + off);
                }
#pragma unroll
                for (int mi = 0; mi < 2; mi++)
#pragma unroll
                    for (int j = 0; j < 4; j++) {
                        float* cc = acc[mi][half * 4 + j];
                        mma16816(cc, ah[mi], bh[j]);
                        mma16816(cc, ah[mi], bl[j]);
                        mma16816(cc, al[mi], bh[j]);
                    }
            }
        }
        __syncthreads();
    }

    // ---- epilogue: bias + store (fp32 or fp16) ----
#pragma unroll
    for (int mi = 0; mi < 2; mi++) {
        int row0 = mBase + warpM + mi * 16 + (lane >> 2);
#pragma unroll
        for (int nj = 0; nj < 8; nj++) {
            int col = nBase + warpN + nj * 8 + (lane & 3) * 2;
            float bx = __ldg(bias + col), by = __ldg(bias + col + 1);
            float v00 = acc[mi][nj][0] + bx, v01 = acc[mi][nj][1] + by;
            float v10 = acc[mi][nj][2] + bx, v11 = acc[mi][nj][3] + by;
            if constexpr (sizeof(OutT) == 4) {
                *(float2*)((float*)C + (size_t)row0 * N + col)       = make_float2(v00, v01);
                *(float2*)((float*)C + (size_t)(row0 + 8) * N + col) = make_float2(v10, v11);
            } else {
                *(__half2*)((__half*)C + (size_t)row0 * N + col)       = __floats2half2_rn(v00, v01);
                *(__half2*)((__half*)C + (size_t)(row0 + 8) * N + col) = __floats2half2_rn(v10, v11);
            }
        }
    }
}

// ---------------------------------------------------------------------------
// Fused softmax + deformable sampling, two-phase, shuffle-free inner loop.
// Block = 256 threads = 2 query rows x 8 heads = 16 head-slots.
// Phase 1: thread (hs, s) computes softmax'd bilinear weights + gather
//          indices for one (head, point) -> smem float4/int4.
// Phase 2: warp w serves head-slots {2w, 2w+1}: lane group (16 lanes) = one
//          head, each lane = 2 channels (__half2). Inner loop per point:
//          2 broadcast LDS.128 + 4 LDG.32 + FMAs. No shuffles.
// ---------------------------------------------------------------------------
__global__ __launch_bounds__(256) void msda_sample(const float* __restrict__ refp)
{
    __shared__ float4 sw[16][16];
    __shared__ int4   si[16][16];

    const int tid = threadIdx.x;
    const int rowBase = blockIdx.x * 2;

    // ---- Phase 1: per-(head,point) setup ----
    {
        const int hs  = tid >> 4;        // head slot 0..15
        const int s   = tid & 15;        // point (lvl*4 + pt)
        const int row = rowBase + (hs >> 3);
        const int h   = hs & 7;
        const int b   = row / LQ;

        const int lvl = s >> 2;
        const int Wl  = 64 >> lvl;
        const int st  = (16384 - (16384 >> (2 * lvl))) / 3;

        const float refx = refp[row * 8 + lvl * 2 + 0];
        const float refy = refp[row * 8 + lvl * 2 + 1];
        const int obase  = row * 384 + ((h * 16 + s) * 2);
        const float offx = g_oa[obase + 0];
        const float offy = g_oa[obase + 1];

        const float x = refx * (float)Wl + offx - 0.5f;
        const float y = refy * (float)Wl + offy - 0.5f;
        const float fx = floorf(x), fy = floorf(y);
        const float lx = x - fx,   ly = y - fy;
        const int x0 = (int)fx, y0 = (int)fy;
        const int x1 = x0 + 1,  y1 = y0 + 1;

        const float logit = g_oa[row * 384 + 256 + h * 16 + s];
        float mx = logit;
#pragma unroll
        for (int o = 8; o; o >>= 1) mx = fmaxf(mx, __shfl_xor_sync(~0u, mx, o, 16));
        const float e = __expf(logit - mx);
        float sum = e;
#pragma unroll
        for (int o = 8; o; o >>= 1) sum += __shfl_xor_sync(~0u, sum, o, 16);
        const float wa = e / sum;

        const bool vx0 = (unsigned)x0 < (unsigned)Wl;
        const bool vx1 = (unsigned)x1 < (unsigned)Wl;
        const bool vy0 = (unsigned)y0 < (unsigned)Wl;
        const bool vy1 = (unsigned)y1 < (unsigned)Wl;
        const int cx0 = min(max(x0, 0), Wl - 1);
        const int cx1 = min(max(x1, 0), Wl - 1);
        const int cy0 = min(max(y0, 0), Wl - 1);
        const int cy1 = min(max(y1, 0), Wl - 1);
        const int rb  = b * LIN + st;

        si[hs][s] = make_int4(rb + cy0 * Wl + cx0, rb + cy0 * Wl + cx1,
                              rb + cy1 * Wl + cx0, rb + cy1 * Wl + cx1);
        sw[hs][s] = make_float4(
            wa * (1.f - lx) * (1.f - ly) * (float)(vx0 && vy0),
            wa * lx         * (1.f - ly) * (float)(vx1 && vy0),
            wa * (1.f - lx) * ly         * (float)(vx0 && vy1),
            wa * lx         * ly         * (float)(vx1 && vy1));
    }
    __syncthreads();

    // ---- Phase 2: gather + accumulate ----
    const int wid  = tid >> 5;
    const int lane = tid & 31;
    const int hs   = wid * 2 + (lane >> 4);
    const int row  = rowBase + (hs >> 3);
    const int h    = hs & 7;
    const int c2   = (lane & 15) * 2;          // channel pair

    const __half* __restrict__ vbase = g_value_h + h * 32 + c2;
    float ax = 0.f, ay = 0.f;
#pragma unroll 4
    for (int t = 0; t < 16; t++) {
        const float4 w  = sw[hs][t];
        const int4   id = si[hs][t];
        const float2 f0 = __half22float2(*(const __half2*)(vbase + (size_t)id.x * 256));
        const float2 f1 = __half22float2(*(const __half2*)(vbase + (size_t)id.y * 256));
        const float2 f2 = __half22float2(*(const __half2*)(vbase + (size_t)id.z * 256));
        const float2 f3 = __half22float2(*(const __half2*)(vbase + (size_t)id.w * 256));
        ax += w.x * f0.x + w.y * f1.x + w.z * f2.x + w.w * f3.x;
        ay += w.x * f0.y + w.y * f1.y + w.z * f2.y + w.w * f3.y;
    }
    *(float2*)(g_core + (size_t)row * 256 + h * 32 + c2) = make_float2(ax, ay);
}

// ---------------------------------------------------------------------------
extern "C" void kernel_launch(void* const* d_in, const int* in_sizes, int n_in,
                              void* d_out, int out_size)
{
    const float* query  = (const float*)d_in[0];
    const float* refp   = (const float*)d_in[1];
    const float* inpf   = (const float*)d_in[2];
    const float* W_val  = (const float*)d_in[5];
    const float* b_val  = (const float*)d_in[6];
    const float* W_off  = (const float*)d_in[7];
    const float* b_off  = (const float*)d_in[8];
    const float* W_attn = (const float*)d_in[9];
    const float* b_attn = (const float*)d_in[10];
    const float* W_out  = (const float*)d_in[11];
    const float* b_out  = (const float*)d_in[12];
    float* out = (float*)d_out;

    __half* p_val;  float *p_oa, *p_core, *p_boa;
    cudaGetSymbolAddress((void**)&p_val,  g_value_h);
    cudaGetSymbolAddress((void**)&p_oa,   g_oa);
    cudaGetSymbolAddress((void**)&p_core, g_core);
    cudaGetSymbolAddress((void**)&p_boa,  g_boa);
    __nv_bfloat16 *wv_h, *wv_l, *woa_h, *woa_l, *wu_h, *wu_l;
    cudaGetSymbolAddress((void**)&wv_h,  g_wv_hi);  cudaGetSymbolAddress((void**)&wv_l,  g_wv_lo);
    cudaGetSymbolAddress((void**)&woa_h, g_woa_hi); cudaGetSymbolAddress((void**)&woa_l, g_woa_lo);
    cudaGetSymbolAddress((void**)&wu_h,  g_wu_hi);  cudaGetSymbolAddress((void**)&wu_l,  g_wu_lo);

    constexpr int SMEM = 131072;
    cudaFuncSetAttribute(gemm_mma<256, float>,  cudaFuncAttributeMaxDynamicSharedMemorySize, SMEM);
    cudaFuncSetAttribute(gemm_mma<256, __half>, cudaFuncAttributeMaxDynamicSharedMemorySize, SMEM);
    cudaFuncSetAttribute(gemm_mma<384, float>,  cudaFuncAttributeMaxDynamicSharedMemorySize, SMEM);

    // Fused weight prep: 229376 elements = 896 blocks x 256
    prep_all<<<896, 256>>>(W_val, W_off, W_attn, W_out, b_off, b_attn);

    const int MT = MTOT / 128;  // 340
    gemm_mma<256, __half><<<dim3(2, MT), 256, SMEM>>>(inpf,  wv_h,  wv_l,  b_val, p_val);
    gemm_mma<384, float ><<<dim3(3, MT), 256, SMEM>>>(query, woa_h, woa_l, p_boa, p_oa);

    // 2 query rows per block
    msda_sample<<<MTOT / 2, 256>>>(refp);

    gemm_mma<256, float ><<<dim3(2, MT), 256, SMEM>>>(p_core, wu_h, wu_l, b_out, out);
}

// round 6
// speedup vs baseline: 2.6668x; 1.0830x over previous
#include <cuda_runtime.h>
#include <cuda_bf16.h>
#include <cuda_fp16.h>
#include <cstdint>

// Problem constants (fixed by the dataset)
#define BB   8
#define LQ   5440
#define LIN  5440
#define DM   256
#define NH   8
#define MTOT (BB * LQ)   // 43520

// ---------------------------------------------------------------------------
// Scratch (device globals; allocation-free per harness rules)
// ---------------------------------------------------------------------------
__device__ __align__(16) __half g_value_h[MTOT * DM];       // fp16 value
__device__ __align__(16) float  g_oa  [MTOT * 384];         // off(256) + attn logits(128)
__device__ __align__(16) float  g_core[MTOT * DM];

// Pre-split / pre-transposed weights, chunk-contiguous bf16 layout:
// element index = ((k>>6)*N + n)*64 + (k&63)   (64-wide K chunks)
__device__ __align__(16) __nv_bfloat16 g_wv_hi [DM * DM],  g_wv_lo [DM * DM];
__device__ __align__(16) __nv_bfloat16 g_woa_hi[DM * 384], g_woa_lo[DM * 384];
__device__ __align__(16) __nv_bfloat16 g_wu_hi [DM * DM],  g_wu_lo [DM * DM];
__device__ __align__(16) float g_boa[384];

// ---------------------------------------------------------------------------
// Helpers (base-target ISA only: ldmatrix / cp.async / mma.sync)
// ---------------------------------------------------------------------------
__device__ __forceinline__ uint32_t smem_u32(const void* p) {
    uint32_t a;
    asm("{ .reg .u64 t; cvta.to.shared.u64 t, %1; cvt.u32.u64 %0, t; }"
        : "=r"(a) : "l"(p));
    return a;
}
__device__ __forceinline__ void ldsm4(uint32_t* d, uint32_t addr) {
    asm volatile("ldmatrix.sync.aligned.m8n8.x4.shared.b16 {%0,%1,%2,%3}, [%4];"
                 : "=r"(d[0]), "=r"(d[1]), "=r"(d[2]), "=r"(d[3]) : "r"(addr));
}
__device__ __forceinline__ void mma16816(float* c, const uint32_t* a,
                                         const uint32_t* b) {
    asm volatile(
        "mma.sync.aligned.m16n8k16.row.col.f32.bf16.bf16.f32 "
        "{%0,%1,%2,%3}, {%4,%5,%6,%7}, {%8,%9}, {%0,%1,%2,%3};"
        : "+f"(c[0]), "+f"(c[1]), "+f"(c[2]), "+f"(c[3])
        : "r"(a[0]), "r"(a[1]), "r"(a[2]), "r"(a[3]), "r"(b[0]), "r"(b[1]));
}
__device__ __forceinline__ void cp16(uint32_t dst, const void* src) {
    asm volatile("cp.async.cg.shared.global [%0], [%1], 16;"
                 :: "r"(dst), "l"(src) : "memory");
}
__device__ __forceinline__ uint32_t sw128(uint32_t b) { return b ^ ((b >> 3) & 0x70); }

// ---------------------------------------------------------------------------
// Fused weight prep: all three weight matrices (val / off+attn combined / out)
// transposed + bf16 hi/lo split into chunk-contiguous layout, plus combined bias.
// ---------------------------------------------------------------------------
__global__ void prep_all(const float* __restrict__ W_val,
                         const float* __restrict__ W_off,
                         const float* __restrict__ W_attn,
                         const float* __restrict__ W_out,
                         const float* __restrict__ b_off,
                         const float* __restrict__ b_attn)
{
    __nv_bfloat16 *wv_h = g_wv_hi,  *wv_l = g_wv_lo;
    __nv_bfloat16 *wa_h = g_woa_hi, *wa_l = g_woa_lo;
    __nv_bfloat16 *wu_h = g_wu_hi,  *wu_l = g_wu_lo;

    int idx = blockIdx.x * 256 + threadIdx.x;
    if (idx < 384)
        g_boa[idx] = idx < 256 ? b_off[idx] : b_attn[idx - 256];

    float v; __nv_bfloat16 *hi, *lo; int o;
    if (idx < 65536) {                       // W_val [256x256]
        int k = idx >> 8, n = idx & 255;
        v = W_val[idx];
        o = (((k >> 6) << 8) + n) * 64 + (k & 63);
        hi = wv_h; lo = wv_l;
    } else if (idx < 65536 + 98304) {        // combined [256x384]
        int t = idx - 65536;
        int k = t / 384, n = t - k * 384;
        v = n < 256 ? W_off[k * 256 + n] : W_attn[k * 128 + (n - 256)];
        o = ((k >> 6) * 384 + n) * 64 + (k & 63);
        hi = wa_h; lo = wa_l;
    } else {                                 // W_out [256x256]
        int t = idx - 65536 - 98304;
        int k = t >> 8, n = t & 255;
        v = W_out[t];
        o = (((k >> 6) << 8) + n) * 64 + (k & 63);
        hi = wu_h; lo = wu_l;
    }
    __nv_bfloat16 h = __float2bfloat16(v);
    hi[o] = h;
    lo[o] = __float2bfloat16(v - __bfloat162float(h));
}

// ---------------------------------------------------------------------------
// mma.sync bf16 GEMM, 3-term split: C[M,N] = A[M,256]*W + bias (fp32-grade).
// CTA: 128x64 tile, 256 thr (8 warps; warp tile 32x32). K: 4 chunks of 64,
// double-buffered smem (48KB/buffer, 96KB total -> 2 CTAs/SM).
// ---------------------------------------------------------------------------
template <int N, typename OutT>
__global__ __launch_bounds__(256, 2) void gemm_mma(
    const float* __restrict__ A,
    const __nv_bfloat16* __restrict__ Bh_g, const __nv_bfloat16* __restrict__ Bl_g,
    const float* __restrict__ bias, OutT* __restrict__ C)
{
    extern __shared__ char smem[];
    constexpr int BUF = 49152;
    constexpr int O_AL = 16384, O_BH = 32768, O_BL = 40960;

    const int tid  = threadIdx.x;
    const int wid  = tid >> 5;
    const int lane = tid & 31;
    const int mBase = blockIdx.y * 128;
    const int nBase = blockIdx.x * 64;
    const int warpM = (wid & 3) * 32;
    const int warpN = (wid >> 2) * 32;

    const float4* Ag  = (const float4*)A;
    const uint4*  Bhg = (const uint4*)Bh_g;
    const uint4*  Blg = (const uint4*)Bl_g;

    float acc[2][4][4];
#pragma unroll
    for (int i = 0; i < 2; i++)
#pragma unroll
        for (int j = 0; j < 4; j++)
#pragma unroll
            for (int k = 0; k < 4; k++) acc[i][j][k] = 0.f;

    // B chunk: 64 n-rows x 64 k x 2 splits = 1024 uint4 total -> 4 cp/thread
    auto loadB = [&](int c, char* buf) {
        uint32_t bh = smem_u32(buf + O_BH), bl = smem_u32(buf + O_BL);
#pragma unroll
        for (int i = 0; i < 2; i++) {
            int f = tid + 256 * i;              // 0..511 per split
            int n = f >> 3, u = f & 7;
            uint32_t so = (n << 7) + (((u ^ (n & 7))) << 4);
            size_t gi = (size_t)(c * N + nBase + n) * 8 + u;
            cp16(bh + so, Bhg + gi);
            cp16(bl + so, Blg + gi);
        }
        asm volatile("cp.async.commit_group;" ::: "memory");
    };

    float4 apf[8];
    auto loadA = [&](int c) {
#pragma unroll
        for (int i = 0; i < 8; i++) {
            int f = tid + 256 * i;              // 0..2047 float4
            int row = f >> 4, q = f & 15;
            apf[i] = Ag[(size_t)(mBase + row) * 64 + c * 16 + q];
        }
    };
    auto storeA = [&](char* buf) {
        char* ah = buf;
        char* al = buf + O_AL;
#pragma unroll
        for (int i = 0; i < 8; i++) {
            int f = tid + 256 * i;
            int row = f >> 4, q = f & 15;
            float4 v = apf[i];
            __nv_bfloat162 h0 = __floats2bfloat162_rn(v.x, v.y);
            __nv_bfloat162 h1 = __floats2bfloat162_rn(v.z, v.w);
            float2 f0 = __bfloat1622float2(h0), f1 = __bfloat1622float2(h1);
            __nv_bfloat162 l0 = __floats2bfloat162_rn(v.x - f0.x, v.y - f0.y);
            __nv_bfloat162 l1 = __floats2bfloat162_rn(v.z - f1.x, v.w - f1.y);
            uint32_t so = sw128(row * 128 + q * 8);
            *(__nv_bfloat162*)(ah + so)     = h0;
            *(__nv_bfloat162*)(ah + so + 4) = h1;
            *(__nv_bfloat162*)(al + so)     = l0;
            *(__nv_bfloat162*)(al + so + 4) = l1;
        }
    };

    loadB(0, smem);
    loadA(0);

    for (int c = 0; c < 4; c++) {
        char* buf = smem + (c & 1) * BUF;
        storeA(buf);
        if (c < 3) loadB(c + 1, smem + ((c + 1) & 1) * BUF);
        if (c < 3) asm volatile("cp.async.wait_group 1;" ::: "memory");
        else       asm volatile("cp.async.wait_group 0;" ::: "memory");
        __syncthreads();
        if (c < 3) loadA(c + 1);

        const uint32_t Ah = smem_u32(buf);
        const uint32_t Al = Ah + O_AL;
        const uint32_t Bh = Ah + O_BH;
        const uint32_t Bl = Ah + O_BL;

#pragma unroll
        for (int kk = 0; kk < 4; kk++) {
            uint32_t ah[2][4], al[2][4];
#pragma unroll
            for (int mi = 0; mi < 2; mi++) {
                int r = warpM + mi * 16 + (lane & 15);
                int u = kk * 2 + (lane >> 4);
                uint32_t off = (r << 7) + (((u ^ (r & 7))) << 4);
                ldsm4(ah[mi], Ah + off);
                ldsm4(al[mi], Al + off);
            }
            uint32_t bh[4][2], bl[4][2];
#pragma unroll
            for (int p = 0; p < 2; p++) {
                int r = warpN + p * 16 + ((lane >> 4) << 3) + (lane & 7);
                int u = kk * 2 + ((lane >> 3) & 1);
                uint32_t off = (r << 7) + (((u ^ (r & 7))) << 4);
                ldsm4(&bh[p * 2][0], Bh + off);
                ldsm4(&bl[p * 2][0], Bl + off);
            }
#pragma unroll
            for (int mi = 0; mi < 2; mi++)
#pragma unroll
                for (int j = 0; j < 4; j++) {
                    float* cc = acc[mi][j];
                    mma16816(cc, ah[mi], bh[j]);
                    mma16816(cc, ah[mi], bl[j]);
                    mma16816(cc, al[mi], bh[j]);
                }
        }
        __syncthreads();
    }

    // ---- epilogue: bias + store (fp32 or fp16) ----
#pragma unroll
    for (int mi = 0; mi < 2; mi++) {
        int row0 = mBase + warpM + mi * 16 + (lane >> 2);
#pragma unroll
        for (int nj = 0; nj < 4; nj++) {
            int col = nBase + warpN + nj * 8 + (lane & 3) * 2;
            float bx = __ldg(bias + col), by = __ldg(bias + col + 1);
            float v00 = acc[mi][nj][0] + bx, v01 = acc[mi][nj][1] + by;
            float v10 = acc[mi][nj][2] + bx, v11 = acc[mi][nj][3] + by;
            if constexpr (sizeof(OutT) == 4) {
                *(float2*)((float*)C + (size_t)row0 * N + col)       = make_float2(v00, v01);
                *(float2*)((float*)C + (size_t)(row0 + 8) * N + col) = make_float2(v10, v11);
            } else {
                *(__half2*)((__half*)C + (size_t)row0 * N + col)       = __floats2half2_rn(v00, v01);
                *(__half2*)((__half*)C + (size_t)(row0 + 8) * N + col) = __floats2half2_rn(v10, v11);
            }
        }
    }
}

// ---------------------------------------------------------------------------
// Fused softmax + deformable sampling, two-phase, shuffle-free inner loop.
// Block = 256 threads = 2 query rows x 8 heads = 16 head-slots.
// Phase 1 computes softmax'd bilinear weights + BYTE offsets into the fp16
// value tensor; phase 2: warp serves 2 heads, lane = channel pair (__half2),
// inner loop = 2 broadcast LDS.128 + 4 LDG.32 + FMAs. No shuffles.
// ---------------------------------------------------------------------------
__global__ __launch_bounds__(256) void msda_sample(const float* __restrict__ refp)
{
    __shared__ float4 sw[16][16];
    __shared__ int4   si[16][16];

    const int tid = threadIdx.x;
    const int rowBase = blockIdx.x * 2;

    // ---- Phase 1: per-(head,point) setup ----
    {
        const int hs  = tid >> 4;        // head slot 0..15
        const int s   = tid & 15;        // point (lvl*4 + pt)
        const int row = rowBase + (hs >> 3);
        const int h   = hs & 7;
        const int b   = row / LQ;

        const int lvl = s >> 2;
        const int Wl  = 64 >> lvl;
        const int st  = (16384 - (16384 >> (2 * lvl))) / 3;

        const float refx = refp[row * 8 + lvl * 2 + 0];
        const float refy = refp[row * 8 + lvl * 2 + 1];
        const int obase  = row * 384 + ((h * 16 + s) * 2);
        const float offx = g_oa[obase + 0];
        const float offy = g_oa[obase + 1];

        const float x = refx * (float)Wl + offx - 0.5f;
        const float y = refy * (float)Wl + offy - 0.5f;
        const float fx = floorf(x), fy = floorf(y);
        const float lx = x - fx,   ly = y - fy;
        const int x0 = (int)fx, y0 = (int)fy;
        const int x1 = x0 + 1,  y1 = y0 + 1;

        const float logit = g_oa[row * 384 + 256 + h * 16 + s];
        float mx = logit;
#pragma unroll
        for (int o = 8; o; o >>= 1) mx = fmaxf(mx, __shfl_xor_sync(~0u, mx, o, 16));
        const float e = __expf(logit - mx);
        float sum = e;
#pragma unroll
        for (int o = 8; o; o >>= 1) sum += __shfl_xor_sync(~0u, sum, o, 16);
        const float wa = e / sum;

        const bool vx0 = (unsigned)x0 < (unsigned)Wl;
        const bool vx1 = (unsigned)x1 < (unsigned)Wl;
        const bool vy0 = (unsigned)y0 < (unsigned)Wl;
        const bool vy1 = (unsigned)y1 < (unsigned)Wl;
        const int cx0 = min(max(x0, 0), Wl - 1);
        const int cx1 = min(max(x1, 0), Wl - 1);
        const int cy0 = min(max(y0, 0), Wl - 1);
        const int cy1 = min(max(y1, 0), Wl - 1);
        const int rb  = b * LIN + st;

        // byte offsets into g_value_h (row stride = 256 halves = 512 B)
        si[hs][s] = make_int4((rb + cy0 * Wl + cx0) << 9, (rb + cy0 * Wl + cx1) << 9,
                              (rb + cy1 * Wl + cx0) << 9, (rb + cy1 * Wl + cx1) << 9);
        sw[hs][s] = make_float4(
            wa * (1.f - lx) * (1.f - ly) * (float)(vx0 && vy0),
            wa * lx         * (1.f - ly) * (float)(vx1 && vy0),
            wa * (1.f - lx) * ly         * (float)(vx0 && vy1),
            wa * lx         * ly         * (float)(vx1 && vy1));
    }
    __syncthreads();

    // ---- Phase 2: gather + accumulate ----
    const int wid  = tid >> 5;
    const int lane = tid & 31;
    const int hs   = wid * 2 + (lane >> 4);
    const int row  = rowBase + (hs >> 3);
    const int h    = hs & 7;
    const int c2   = (lane & 15) * 2;          // channel pair

    const char* __restrict__ vbase = (const char*)(g_value_h + h * 32 + c2);
    float ax = 0.f, ay = 0.f;
#pragma unroll 4
    for (int t = 0; t < 16; t++) {
        const float4 w  = sw[hs][t];
        const int4   id = si[hs][t];
        const float2 f0 = __half22float2(*(const __half2*)(vbase + id.x));
        const float2 f1 = __half22float2(*(const __half2*)(vbase + id.y));
        const float2 f2 = __half22float2(*(const __half2*)(vbase + id.z));
        const float2 f3 = __half22float2(*(const __half2*)(vbase + id.w));
        ax += w.x * f0.x + w.y * f1.x + w.z * f2.x + w.w * f3.x;
        ay += w.x * f0.y + w.y * f1.y + w.z * f2.y + w.w * f3.y;
    }
    *(float2*)(g_core + (size_t)row * 256 + h * 32 + c2) = make_float2(ax, ay);
}

// ---------------------------------------------------------------------------
extern "C" void kernel_launch(void* const* d_in, const int* in_sizes, int n_in,
                              void* d_out, int out_size)
{
    const float* query  = (const float*)d_in[0];
    const float* refp   = (const float*)d_in[1];
    const float* inpf   = (const float*)d_in[2];
    const float* W_val  = (const float*)d_in[5];
    const float* b_val  = (const float*)d_in[6];
    const float* W_off  = (const float*)d_in[7];
    const float* b_off  = (const float*)d_in[8];
    const float* W_attn = (const float*)d_in[9];
    const float* b_attn = (const float*)d_in[10];
    const float* W_out  = (const float*)d_in[11];
    const float* b_out  = (const float*)d_in[12];
    float* out = (float*)d_out;

    __half* p_val;  float *p_oa, *p_core, *p_boa;
    cudaGetSymbolAddress((void**)&p_val,  g_value_h);
    cudaGetSymbolAddress((void**)&p_oa,   g_oa);
    cudaGetSymbolAddress((void**)&p_core, g_core);
    cudaGetSymbolAddress((void**)&p_boa,  g_boa);
    __nv_bfloat16 *wv_h, *wv_l, *woa_h, *woa_l, *wu_h, *wu_l;
    cudaGetSymbolAddress((void**)&wv_h,  g_wv_hi);  cudaGetSymbolAddress((void**)&wv_l,  g_wv_lo);
    cudaGetSymbolAddress((void**)&woa_h, g_woa_hi); cudaGetSymbolAddress((void**)&woa_l, g_woa_lo);
    cudaGetSymbolAddress((void**)&wu_h,  g_wu_hi);  cudaGetSymbolAddress((void**)&wu_l,  g_wu_lo);

    constexpr int SMEM = 98304;
    cudaFuncSetAttribute(gemm_mma<256, float>,  cudaFuncAttributeMaxDynamicSharedMemorySize, SMEM);
    cudaFuncSetAttribute(gemm_mma<256, __half>, cudaFuncAttributeMaxDynamicSharedMemorySize, SMEM);
    cudaFuncSetAttribute(gemm_mma<384, float>,  cudaFuncAttributeMaxDynamicSharedMemorySize, SMEM);

    // Fused weight prep: 229376 elements = 896 blocks x 256
    prep_all<<<896, 256>>>(W_val, W_off, W_attn, W_out, b_off, b_attn);

    const int MT = MTOT / 128;  // 340
    gemm_mma<256, __half><<<dim3(4, MT), 256, SMEM>>>(inpf,  wv_h,  wv_l,  b_val, p_val);
    gemm_mma<384, float ><<<dim3(6, MT), 256, SMEM>>>(query, woa_h, woa_l, p_boa, p_oa);

    // 2 query rows per block
    msda_sample<<<MTOT / 2, 256>>>(refp);

    gemm_mma<256, float ><<<dim3(4, MT), 256, SMEM>>>(p_core, wu_h, wu_l, b_out, out);
}